// round 5
// baseline (speedup 1.0000x reference)
#include <cuda_runtime.h>
#include <math.h>

// ---------------- problem constants ----------------
#define NB   8
#define ND   768
#define NCH  3
#define NMIX 5
#define NS   10
#define H    10
#define PI2f 6.2831853071795864769f
// C = -0.5*(2pi)^2 * log2(e)  (fold exp->exp2)
#define CEXP (-28.47813296f)
#define ZITTER 1e-4f

// ---------------- device scratch ----------------
__device__ float2 g_tab[NB * NCH * NMIX * ND];   // (cos,sin)(2pi*mu_m*x_j)
__device__ float  g_xr[NB * NCH * ND];
__device__ float  g_yr[NB * NCH * ND];
#define NSEG 6                                   // 6 row-tiles of 128 for k1
__device__ float  g_fpart[NSEG][NB * ND * NCH * NMIX];
__device__ float  g_w[NB * NCH * NMIX];

__device__ __forceinline__ float ex2f(float x) {
    float y;
    asm("ex2.approx.ftz.f32 %0, %1;" : "=f"(y) : "f"(x));
    return y;
}

// ============ Kernel 0: trig tables ============
// grid: (bc, m), block = 768
__global__ void k0_tables(const float* __restrict__ xc,
                          const float* __restrict__ yc,
                          const float* __restrict__ mu) {
    int bc = blockIdx.x;
    int m  = blockIdx.y;
    int b = bc / NCH, c = bc % NCH;
    int j = threadIdx.x;
    float x = xc[(b * ND + j) * NCH + c];
    if (m == 0) {
        g_xr[bc * ND + j] = x;
        g_yr[bc * ND + j] = yc[(b * ND + j) * NCH + c];
    }
    float s, co;
    __sincosf(PI2f * mu[m] * x, &s, &co);
    g_tab[(bc * NMIX + m) * ND + j] = make_float2(co, s);
}

// ============ Kernel 1: feature partials, symmetric tile pairs ============
// 6 row-tiles of 128 -> 21 pairs. grid (21, 3, 8), block 128.
#define T1 128
#define NT1 6
#define NP1 21
__global__ void k1_feature(const float* __restrict__ inv_std) {
    __shared__ float  x_sh[T1];
    __shared__ float  y_sh[T1];
    __shared__ float2 cs_sh[NMIX * T1];
    __shared__ float  fj_sh[4 * NMIX * T1];   // warp-private j-side accumulators

    int p = blockIdx.x;
    int c = blockIdx.y, b = blockIdx.z;
    int bc = b * NCH + c;
    int tid = threadIdx.x;

    // decode pair (ti <= tj)
    int ti = 0, rem = p, cnt = NT1;
    while (rem >= cnt) { rem -= cnt; cnt--; ti++; }
    int tj = ti + rem;

    int j0 = tj * T1;
    // stage j-side
    x_sh[tid] = g_xr[bc * ND + j0 + tid];
    y_sh[tid] = g_yr[bc * ND + j0 + tid];
#pragma unroll
    for (int m = 0; m < NMIX; m++)
        cs_sh[m * T1 + tid] = g_tab[(bc * NMIX + m) * ND + j0 + tid];
    for (int t = tid; t < 4 * NMIX * T1; t += T1) fj_sh[t] = 0.f;
    __syncthreads();

    // i-side (registers)
    int i = ti * T1 + tid;
    float xi = g_xr[bc * ND + i];
    float yi = g_yr[bc * ND + i];
    float ci[NMIX], si[NMIX], am[NMIX], acc[NMIX];
#pragma unroll
    for (int m = 0; m < NMIX; m++) {
        float2 cs = g_tab[(bc * NMIX + m) * ND + i];
        ci[m] = cs.x; si[m] = cs.y;
        float iv = __ldg(&inv_std[m]);
        am[m] = CEXP * iv * iv;
        acc[m] = 0.f;
    }

    if (ti != tj) {
        int w = tid >> 5;
        float* fjw = &fj_sh[w * NMIX * T1];
#pragma unroll 2
        for (int s = 0; s < T1; s++) {
            int jl = (tid + s) & (T1 - 1);
            float xj = x_sh[jl];
            float yj = y_sh[jl];
            float d = xi - xj;
            float t2 = d * d;
#pragma unroll
            for (int m = 0; m < NMIX; m++) {
                float2 cs = cs_sh[m * T1 + jl];
                float e = ex2f(am[m] * t2);
                float pr = fmaf(si[m], cs.y, ci[m] * cs.x);
                float K = e * pr;
                acc[m] = fmaf(K, yj, acc[m]);
                fjw[m * T1 + jl] = fmaf(K, yi, fjw[m * T1 + jl]);
            }
        }
    } else {
        // diagonal tile: full loop, i-side accumulation only
#pragma unroll 2
        for (int jl = 0; jl < T1; jl++) {
            float xj = x_sh[jl];
            float yj = y_sh[jl];
            float d = xi - xj;
            float t2 = d * d;
#pragma unroll
            for (int m = 0; m < NMIX; m++) {
                float2 cs = cs_sh[m * T1 + jl];
                float e = ex2f(am[m] * t2);
                float pr = fmaf(si[m], cs.y, ci[m] * cs.x);
                acc[m] = fmaf(e * pr, yj, acc[m]);
            }
        }
    }
    __syncthreads();

    // i-side partial -> segment tj
    int basei = ((b * ND + i) * NCH + c) * NMIX;
#pragma unroll
    for (int m = 0; m < NMIX; m++)
        g_fpart[tj][basei + m] = acc[m];

    // j-side partial -> segment ti (reduce the 4 warp copies)
    if (ti != tj) {
        int jg = j0 + tid;
        int basej = ((b * ND + jg) * NCH + c) * NMIX;
#pragma unroll
        for (int m = 0; m < NMIX; m++) {
            float s = fj_sh[(0 * NMIX + m) * T1 + tid]
                    + fj_sh[(1 * NMIX + m) * T1 + tid]
                    + fj_sh[(2 * NMIX + m) * T1 + tid]
                    + fj_sh[(3 * NMIX + m) * T1 + tid];
            g_fpart[ti][basej + m] = s;
        }
    }
}

// ============ Kernel 2: MLP + Gumbel softmax -> mixture weights ============
__global__ void k2_mlp(const float* __restrict__ yc,
                       const float* __restrict__ unif,
                       const float* __restrict__ W1, const float* __restrict__ b1,
                       const float* __restrict__ W2, const float* __restrict__ b2,
                       const float* __restrict__ W3, const float* __restrict__ b3,
                       const float* __restrict__ W4, const float* __restrict__ b4,
                       const float* __restrict__ W5, const float* __restrict__ b5) {
    __shared__ float s_part[256 * 30];
    __shared__ float s_r8[8 * 30];
    __shared__ float s_W1[60], s_b1[10];
    __shared__ float s_hm[30];
    __shared__ float s_ha[10], s_hb[10];
    __shared__ float s_ll[15];

    int b = blockIdx.x;
    int tid = threadIdx.x;
    if (tid < 60) s_W1[tid] = W1[tid];
    if (tid < 10) s_b1[tid] = b1[tid];
    __syncthreads();

    float acc30[30];
#pragma unroll
    for (int q = 0; q < 30; q++) acc30[q] = 0.f;

    for (int rep = 0; rep < 3; rep++) {
        int i = tid + rep * 256;
#pragma unroll
        for (int c = 0; c < NCH; c++) {
            int base = ((b * ND + i) * NCH + c) * NMIX;
            float y = yc[(b * ND + i) * NCH + c];
            float tif[6];
#pragma unroll
            for (int m = 0; m < NMIX; m++) {
                float f = ZITTER * y;
#pragma unroll
                for (int s = 0; s < NSEG; s++) f += g_fpart[s][base + m];
                tif[m] = f;
            }
            tif[5] = y;
#pragma unroll
            for (int k = 0; k < H; k++) {
                float h = s_b1[k];
#pragma unroll
                for (int q = 0; q < 6; q++) h = fmaf(tif[q], s_W1[k * 6 + q], h);
                acc30[c * H + k] += fmaxf(h, 0.f);
            }
        }
    }
#pragma unroll
    for (int q = 0; q < 30; q++) s_part[tid * 30 + q] = acc30[q];
    __syncthreads();

    if (tid < 240) {
        int q = tid >> 3, pp = tid & 7;
        float s = 0.f;
        int t0 = pp * 32;
#pragma unroll 4
        for (int t = t0; t < t0 + 32; t++) s += s_part[t * 30 + q];
        s_r8[pp * 30 + q] = s;
    }
    __syncthreads();
    if (tid < 30) {
        float s = 0.f;
#pragma unroll
        for (int pp = 0; pp < 8; pp++) s += s_r8[pp * 30 + tid];
        s_hm[tid] = s / (float)ND;
    }
    __syncthreads();

    if (tid < 10) {
        float v = b2[tid];
        for (int q = 0; q < 30; q++) v = fmaf(s_hm[q], W2[tid * 30 + q], v);
        s_ha[tid] = fmaxf(v, 0.f);
    }
    __syncthreads();
    if (tid < 10) {
        float v = b3[tid];
        for (int q = 0; q < 10; q++) v = fmaf(s_ha[q], W3[tid * 10 + q], v);
        s_hb[tid] = fmaxf(v, 0.f);
    }
    __syncthreads();
    if (tid < 10) {
        float v = b4[tid];
        for (int q = 0; q < 10; q++) v = fmaf(s_hb[q], W4[tid * 10 + q], v);
        s_ha[tid] = fmaxf(v, 0.f);
    }
    __syncthreads();
    if (tid < 15) {
        float v = b5[tid];
        for (int q = 0; q < 10; q++) v = fmaf(s_ha[q], W5[tid * 10 + q], v);
        s_ll[tid] = v;
    }
    __syncthreads();

    if (tid < 15) {
        int c = tid / NMIX, m = tid % NMIX;
        float wacc = 0.f;
        for (int s = 0; s < NS; s++) {
            float z[NMIX], zmax = -1e30f;
#pragma unroll
            for (int mp = 0; mp < NMIX; mp++) {
                float u = unif[((b * NS + s) * NCH + c) * NMIX + mp];
                float g = -logf(-logf(u + 1e-20f));
                z[mp] = (g + s_ll[c * NMIX + mp]) * 10.0f;
                zmax = fmaxf(zmax, z[mp]);
            }
            float denom = 0.f, em = 0.f;
#pragma unroll
            for (int mp = 0; mp < NMIX; mp++) {
                float e = __expf(z[mp] - zmax);
                denom += e;
                if (mp == m) em = e;
            }
            wacc += em / denom;
        }
        g_w[(b * NCH + c) * NMIX + m] = wacc / (float)NS;
    }
}

// ============ Kernel 3: weighted output, symmetric tile pairs ============
// 12 tiles of 64 -> 78 pairs. grid (78, 8), block 256 = 64 j x 4 i-groups.
#define T3 64
#define NT3 12
#define NP3 78
__global__ void __launch_bounds__(256, 4) k3_weighted(
        const float* __restrict__ likerr,
        const float* __restrict__ inv_std,
        float* __restrict__ out) {
    __shared__ float  s_xi[T3 * NCH];
    __shared__ float2 s_w2[T3 * NCH * NMIX];   // (w*cos_i, w*sin_i)

    int p = blockIdx.x;
    int b = blockIdx.y;
    int tid = threadIdx.x;
    int jl = tid & (T3 - 1);
    int ig = tid >> 6;          // 0..3

    int ti = 0, rem = p, cnt = NT3;
    while (rem >= cnt) { rem -= cnt; cnt--; ti++; }
    int tj = ti + rem;
    int i0 = ti * T3;
    int j  = tj * T3 + jl;

    // ---- j-side into registers ----
    float xj[NCH], cj[NCH][NMIX], sj[NCH][NMIX];
#pragma unroll
    for (int c = 0; c < NCH; c++) {
        int bc = b * NCH + c;
        xj[c] = g_xr[bc * ND + j];
#pragma unroll
        for (int m = 0; m < NMIX; m++) {
            float2 cs = g_tab[(bc * NMIX + m) * ND + j];
            cj[c][m] = cs.x; sj[c][m] = cs.y;
        }
    }
    float am[NMIX];
#pragma unroll
    for (int m = 0; m < NMIX; m++) {
        float iv = __ldg(&inv_std[m]);
        am[m] = CEXP * iv * iv;
    }
    float dg[NCH];
#pragma unroll
    for (int c = 0; c < NCH; c++) {
        float lv = fminf(fmaxf(__ldg(&likerr[c]), 0.1f), 1.0f);
        dg[c] = ZITTER + lv * lv;
    }

    // ---- stage i-side tile ----
    for (int t = tid; t < T3 * NCH * NMIX; t += 256) {
        int ii = t / (NCH * NMIX);
        int cm = t % (NCH * NMIX);
        int c = cm / NMIX, m = cm % NMIX;
        int bc = b * NCH + c;
        float2 cs = g_tab[(bc * NMIX + m) * ND + (i0 + ii)];
        float ww = g_w[bc * NMIX + m];
        s_w2[t] = make_float2(ww * cs.x, ww * cs.y);
    }
    for (int t = tid; t < T3 * NCH; t += 256) {
        int ii = t / NCH, c = t % NCH;
        s_xi[t] = g_xr[(b * NCH + c) * ND + (i0 + ii)];
    }
    __syncthreads();

    bool offdiag = (ti != tj);

    // ---- main loop: 16 i per thread ----
#pragma unroll 2
    for (int k = 0; k < 16; k++) {
        int ii = ig * 16 + k;
        int i = i0 + ii;
        float res[NCH];
#pragma unroll
        for (int c = 0; c < NCH; c++) {
            float d = s_xi[ii * NCH + c] - xj[c];
            float t2 = d * d;
            float acc = 0.f;
            int base = (ii * NCH + c) * NMIX;
#pragma unroll
            for (int m = 0; m < NMIX; m++) {
                float2 w2 = s_w2[base + m];
                float e = ex2f(am[m] * t2);
                float pr = fmaf(w2.y, sj[c][m], w2.x * cj[c][m]);
                acc = fmaf(e, pr, acc);
            }
            res[c] = acc;
        }
        // direct store (i,j): coalesced over jl
        int dbase = ((b * ND + i) * ND + j) * NCH;
        if (!offdiag && j == i) {
            out[dbase + 0] = res[0] + dg[0];
            out[dbase + 1] = res[1] + dg[1];
            out[dbase + 2] = res[2] + dg[2];
        } else {
            out[dbase + 0] = res[0];
            out[dbase + 1] = res[1];
            out[dbase + 2] = res[2];
        }
        // mirror store (j,i)
        if (offdiag) {
            int mbase = ((b * ND + j) * ND + i) * NCH;
            out[mbase + 0] = res[0];
            out[mbase + 1] = res[1];
            out[mbase + 2] = res[2];
        }
    }
}

// ---------------- launch ----------------
extern "C" void kernel_launch(void* const* d_in, const int* in_sizes, int n_in,
                              void* d_out, int out_size) {
    const float* xc      = (const float*)d_in[0];
    const float* yc      = (const float*)d_in[1];
    const float* mu      = (const float*)d_in[2];
    const float* inv_std = (const float*)d_in[3];
    const float* likerr  = (const float*)d_in[4];
    const float* unif    = (const float*)d_in[5];
    const float* W1 = (const float*)d_in[6];
    const float* b1 = (const float*)d_in[7];
    const float* W2 = (const float*)d_in[8];
    const float* b2 = (const float*)d_in[9];
    const float* W3 = (const float*)d_in[10];
    const float* b3 = (const float*)d_in[11];
    const float* W4 = (const float*)d_in[12];
    const float* b4 = (const float*)d_in[13];
    const float* W5 = (const float*)d_in[14];
    const float* b5 = (const float*)d_in[15];
    float* out = (float*)d_out;

    k0_tables<<<dim3(NB * NCH, NMIX), ND>>>(xc, yc, mu);
    k1_feature<<<dim3(NP1, NCH, NB), T1>>>(inv_std);
    k2_mlp<<<NB, 256>>>(yc, unif, W1, b1, W2, b2, W3, b3, W4, b4, W5, b5);
    k3_weighted<<<dim3(NP3, NB), 256>>>(likerr, inv_std, out);
}

// round 8
// speedup vs baseline: 1.5306x; 1.5306x over previous
#include <cuda_runtime.h>
#include <math.h>

// ---------------- problem constants ----------------
#define NB   8
#define ND   768
#define NCH  3
#define NMIX 5
#define NS   10
#define H    10
#define PI2f 6.2831853071795864769f
// C = -0.5*(2pi)^2 * log2(e)  (fold exp->exp2)
#define CEXP (-28.47813296f)
#define ZITTER 1e-4f

// ---------------- device scratch ----------------
__device__ float2 g_tab[NB * NCH * NMIX * ND];   // (cos,sin)(2pi*mu_m*x_j)
__device__ float2 g_tabY[NB * NCH * NMIX * ND];  // y-premultiplied
__device__ float  g_xr[NB * NCH * ND];
#define NSEG 4
#define JSEG 192
__device__ float  g_fpart[NSEG][NB * ND * NCH * NMIX];
__device__ float  g_w[NB * NCH * NMIX];

__device__ __forceinline__ float ex2f(float x) {
    float y;
    asm("ex2.approx.ftz.f32 %0, %1;" : "=f"(y) : "f"(x));
    return y;
}

// ============ Kernel 0: trig tables (+ y-premultiplied) ============
__global__ void k0_tables(const float* __restrict__ xc,
                          const float* __restrict__ yc,
                          const float* __restrict__ mu) {
    int bc = blockIdx.x;
    int b = bc / NCH, c = bc % NCH;
    int j = threadIdx.x;
    float x = xc[(b * ND + j) * NCH + c];
    float y = yc[(b * ND + j) * NCH + c];
    g_xr[bc * ND + j] = x;
#pragma unroll
    for (int m = 0; m < NMIX; m++) {
        float s, co;
        sincosf(PI2f * mu[m] * x, &s, &co);
        g_tab [(bc * NMIX + m) * ND + j] = make_float2(co, s);
        g_tabY[(bc * NMIX + m) * ND + j] = make_float2(co * y, s * y);
    }
}

// ============ Kernel 1: feature partials (r4 proven version) ============
// grid: x = 6 i-tiles * 4 j-segs, y = c, z = b; block = 128 (576 blocks)
__global__ void k1_feature(const float* __restrict__ inv_std) {
    __shared__ float  x_sh[JSEG];
    __shared__ float2 tabY[NMIX * JSEG];

    int seg  = blockIdx.x & 3;
    int tile = blockIdx.x >> 2;
    int c = blockIdx.y, b = blockIdx.z;
    int bc = b * NCH + c;
    int tid = threadIdx.x;
    int j0 = seg * JSEG;

    for (int t = tid; t < JSEG; t += 128)
        x_sh[t] = g_xr[bc * ND + j0 + t];
    for (int idx = tid; idx < NMIX * JSEG; idx += 128) {
        int m = idx / JSEG, jl = idx % JSEG;
        tabY[idx] = g_tabY[(bc * NMIX + m) * ND + j0 + jl];
    }
    __syncthreads();

    int i = tile * 128 + tid;
    float xi = g_xr[bc * ND + i];
    float ci[NMIX], si[NMIX], am[NMIX], acc[NMIX];
#pragma unroll
    for (int m = 0; m < NMIX; m++) {
        float2 cs = g_tab[(bc * NMIX + m) * ND + i];
        ci[m] = cs.x; si[m] = cs.y;
        float iv = __ldg(&inv_std[m]);
        am[m] = CEXP * iv * iv;
        acc[m] = 0.f;
    }

#pragma unroll 4
    for (int jl = 0; jl < JSEG; jl++) {
        float d = xi - x_sh[jl];
        float t = d * d;
#pragma unroll
        for (int m = 0; m < NMIX; m++) {
            float2 cy = tabY[m * JSEG + jl];
            float e = ex2f(am[m] * t);
            float p = fmaf(si[m], cy.y, ci[m] * cy.x);
            acc[m] = fmaf(e, p, acc[m]);
        }
    }

    int base = ((b * ND + i) * NCH + c) * NMIX;
#pragma unroll
    for (int m = 0; m < NMIX; m++)
        g_fpart[seg][base + m] = acc[m];
}

// ============ Kernel 2: MLP + Gumbel softmax -> mixture weights ============
__global__ void k2_mlp(const float* __restrict__ yc,
                       const float* __restrict__ unif,
                       const float* __restrict__ W1, const float* __restrict__ b1,
                       const float* __restrict__ W2, const float* __restrict__ b2,
                       const float* __restrict__ W3, const float* __restrict__ b3,
                       const float* __restrict__ W4, const float* __restrict__ b4,
                       const float* __restrict__ W5, const float* __restrict__ b5) {
    __shared__ float s_part[256 * 30];
    __shared__ float s_r8[8 * 30];
    __shared__ float s_W1[60], s_b1[10];
    __shared__ float s_hm[30];
    __shared__ float s_ha[10], s_hb[10];
    __shared__ float s_ll[15];

    int b = blockIdx.x;
    int tid = threadIdx.x;
    if (tid < 60) s_W1[tid] = W1[tid];
    if (tid < 10) s_b1[tid] = b1[tid];
    __syncthreads();

    float acc30[30];
#pragma unroll
    for (int q = 0; q < 30; q++) acc30[q] = 0.f;

    for (int rep = 0; rep < 3; rep++) {
        int i = tid + rep * 256;
#pragma unroll
        for (int c = 0; c < NCH; c++) {
            int base = ((b * ND + i) * NCH + c) * NMIX;
            float y = yc[(b * ND + i) * NCH + c];
            float tif[6];
#pragma unroll
            for (int m = 0; m < NMIX; m++) {
                float f = ZITTER * y;
#pragma unroll
                for (int s = 0; s < NSEG; s++) f += g_fpart[s][base + m];
                tif[m] = f;
            }
            tif[5] = y;
#pragma unroll
            for (int k = 0; k < H; k++) {
                float h = s_b1[k];
#pragma unroll
                for (int q = 0; q < 6; q++) h = fmaf(tif[q], s_W1[k * 6 + q], h);
                acc30[c * H + k] += fmaxf(h, 0.f);
            }
        }
    }
#pragma unroll
    for (int q = 0; q < 30; q++) s_part[tid * 30 + q] = acc30[q];
    __syncthreads();

    if (tid < 240) {
        int q = tid >> 3, pp = tid & 7;
        float s = 0.f;
        int t0 = pp * 32;
#pragma unroll 4
        for (int t = t0; t < t0 + 32; t++) s += s_part[t * 30 + q];
        s_r8[pp * 30 + q] = s;
    }
    __syncthreads();
    if (tid < 30) {
        float s = 0.f;
#pragma unroll
        for (int pp = 0; pp < 8; pp++) s += s_r8[pp * 30 + tid];
        s_hm[tid] = s / (float)ND;
    }
    __syncthreads();

    if (tid < 10) {
        float v = b2[tid];
        for (int q = 0; q < 30; q++) v = fmaf(s_hm[q], W2[tid * 30 + q], v);
        s_ha[tid] = fmaxf(v, 0.f);
    }
    __syncthreads();
    if (tid < 10) {
        float v = b3[tid];
        for (int q = 0; q < 10; q++) v = fmaf(s_ha[q], W3[tid * 10 + q], v);
        s_hb[tid] = fmaxf(v, 0.f);
    }
    __syncthreads();
    if (tid < 10) {
        float v = b4[tid];
        for (int q = 0; q < 10; q++) v = fmaf(s_hb[q], W4[tid * 10 + q], v);
        s_ha[tid] = fmaxf(v, 0.f);
    }
    __syncthreads();
    if (tid < 15) {
        float v = b5[tid];
        for (int q = 0; q < 10; q++) v = fmaf(s_ha[q], W5[tid * 10 + q], v);
        s_ll[tid] = v;
    }
    __syncthreads();

    if (tid < 15) {
        int c = tid / NMIX, m = tid % NMIX;
        float wacc = 0.f;
        for (int s = 0; s < NS; s++) {
            float z[NMIX], zmax = -1e30f;
#pragma unroll
            for (int mp = 0; mp < NMIX; mp++) {
                float u = unif[((b * NS + s) * NCH + c) * NMIX + mp];
                float g = -logf(-logf(u + 1e-20f));
                z[mp] = (g + s_ll[c * NMIX + mp]) * 10.0f;
                zmax = fmaxf(zmax, z[mp]);
            }
            float denom = 0.f, em = 0.f;
#pragma unroll
            for (int mp = 0; mp < NMIX; mp++) {
                float e = __expf(z[mp] - zmax);
                denom += e;
                if (mp == m) em = e;
            }
            wacc += em / denom;
        }
        g_w[(b * NCH + c) * NMIX + m] = wacc / (float)NS;
    }
}

// ============ Kernel 3: symmetric tile pairs + smem-transposed mirror ======
// 12 tiles of 64 -> 78 pairs. grid (78, 8), block 256 = 64 j x 4 i-groups.
// Mirror values transposed through smem so BOTH stores are coalesced.
#define T3 64
#define NT3 12
#define NP3 78
#define HROWS 32                 // rows buffered per half
__global__ void __launch_bounds__(256) k3_weighted(
        const float* __restrict__ likerr,
        const float* __restrict__ inv_std,
        float* __restrict__ out) {
    __shared__ float  s_xi[T3 * NCH];
    __shared__ float2 s_w2[T3 * NCH * NMIX];      // (w*cos_i, w*sin_i)
    __shared__ float  s_buf[HROWS * 65 * NCH];    // [iloc*65+jl][c], padded

    int p = blockIdx.x;
    int b = blockIdx.y;
    int tid = threadIdx.x;
    int jl = tid & (T3 - 1);
    int ig = tid >> 6;          // 0..3

    int ti = 0, rem = p, cnt = NT3;
    while (rem >= cnt) { rem -= cnt; cnt--; ti++; }
    int tj = ti + rem;
    int i0 = ti * T3;
    int j0 = tj * T3;
    int j  = j0 + jl;
    bool offdiag = (ti != tj);

    // ---- j-side into registers ----
    float xj[NCH], cj[NCH][NMIX], sj[NCH][NMIX];
#pragma unroll
    for (int c = 0; c < NCH; c++) {
        int bc = b * NCH + c;
        xj[c] = g_xr[bc * ND + j];
#pragma unroll
        for (int m = 0; m < NMIX; m++) {
            float2 cs = g_tab[(bc * NMIX + m) * ND + j];
            cj[c][m] = cs.x; sj[c][m] = cs.y;
        }
    }
    float am[NMIX];
#pragma unroll
    for (int m = 0; m < NMIX; m++) {
        float iv = __ldg(&inv_std[m]);
        am[m] = CEXP * iv * iv;
    }
    float dg[NCH];
#pragma unroll
    for (int c = 0; c < NCH; c++) {
        float lv = fminf(fmaxf(__ldg(&likerr[c]), 0.1f), 1.0f);
        dg[c] = ZITTER + lv * lv;
    }

    // ---- stage i-side tile ----
    for (int t = tid; t < T3 * NCH * NMIX; t += 256) {
        int ii = t / (NCH * NMIX);
        int cm = t % (NCH * NMIX);
        int c = cm / NMIX, m = cm % NMIX;
        int bc = b * NCH + c;
        float2 cs = g_tab[(bc * NMIX + m) * ND + (i0 + ii)];
        float ww = g_w[bc * NMIX + m];
        s_w2[t] = make_float2(ww * cs.x, ww * cs.y);
    }
    for (int t = tid; t < T3 * NCH; t += 256) {
        int ii = t / NCH, c = t % NCH;
        s_xi[t] = g_xr[(b * NCH + c) * ND + (i0 + ii)];
    }
    __syncthreads();

    // two halves of 32 i-rows each
#pragma unroll
    for (int h = 0; h < 2; h++) {
        // compute phase: each ig group does 8 rows of this half
#pragma unroll 2
        for (int k = 0; k < 8; k++) {
            int iloc = ig * 8 + k;          // 0..31 within half
            int ii = h * HROWS + iloc;      // 0..63
            int i = i0 + ii;
            float res[NCH];
#pragma unroll
            for (int c = 0; c < NCH; c++) {
                float d = s_xi[ii * NCH + c] - xj[c];
                float t2 = d * d;
                float acc = 0.f;
                int base = (ii * NCH + c) * NMIX;
#pragma unroll
                for (int m = 0; m < NMIX; m++) {
                    float2 w2 = s_w2[base + m];
                    float e = ex2f(am[m] * t2);
                    float pr = fmaf(w2.y, sj[c][m], w2.x * cj[c][m]);
                    acc = fmaf(e, pr, acc);
                }
                res[c] = acc;
            }
            // direct store (i,j): coalesced over jl
            int dbase = ((b * ND + i) * ND + j) * NCH;
            if (!offdiag && j == i) {
                out[dbase + 0] = res[0] + dg[0];
                out[dbase + 1] = res[1] + dg[1];
                out[dbase + 2] = res[2] + dg[2];
            } else {
                out[dbase + 0] = res[0];
                out[dbase + 1] = res[1];
                out[dbase + 2] = res[2];
            }
            // deposit for mirror
            if (offdiag) {
                int bi = (iloc * 65 + jl) * NCH;
                s_buf[bi + 0] = res[0];
                s_buf[bi + 1] = res[1];
                s_buf[bi + 2] = res[2];
            }
        }
        __syncthreads();
        // mirror phase: lane owns i (coalesced store), loop over j
        if (offdiag) {
            int il = tid & (HROWS - 1);     // 0..31 (i within half)
            int jg = tid >> 5;              // 0..7, each does 8 jl
            int i = i0 + h * HROWS + il;
#pragma unroll 2
            for (int t = 0; t < 8; t++) {
                int jl2 = jg * 8 + t;
                int bi = (il * 65 + jl2) * NCH;
                int mbase = ((b * ND + (j0 + jl2)) * ND + i) * NCH;
                out[mbase + 0] = s_buf[bi + 0];
                out[mbase + 1] = s_buf[bi + 1];
                out[mbase + 2] = s_buf[bi + 2];
            }
        }
        __syncthreads();
    }
}

// ---------------- launch ----------------
extern "C" void kernel_launch(void* const* d_in, const int* in_sizes, int n_in,
                              void* d_out, int out_size) {
    const float* xc      = (const float*)d_in[0];
    const float* yc      = (const float*)d_in[1];
    const float* mu      = (const float*)d_in[2];
    const float* inv_std = (const float*)d_in[3];
    const float* likerr  = (const float*)d_in[4];
    const float* unif    = (const float*)d_in[5];
    const float* W1 = (const float*)d_in[6];
    const float* b1 = (const float*)d_in[7];
    const float* W2 = (const float*)d_in[8];
    const float* b2 = (const float*)d_in[9];
    const float* W3 = (const float*)d_in[10];
    const float* b3 = (const float*)d_in[11];
    const float* W4 = (const float*)d_in[12];
    const float* b4 = (const float*)d_in[13];
    const float* W5 = (const float*)d_in[14];
    const float* b5 = (const float*)d_in[15];
    float* out = (float*)d_out;

    k0_tables<<<NB * NCH, ND>>>(xc, yc, mu);
    k1_feature<<<dim3(6 * NSEG, NCH, NB), 128>>>(inv_std);
    k2_mlp<<<NB, 256>>>(yc, unif, W1, b1, W2, b2, W3, b3, W4, b4, W5, b5);
    k3_weighted<<<dim3(NP3, NB), 256>>>(likerr, inv_std, out);
}

// round 9
// speedup vs baseline: 1.7373x; 1.1351x over previous
#include <cuda_runtime.h>
#include <math.h>

// ---------------- problem constants ----------------
#define NB   8
#define ND   768
#define NCH  3
#define NMIX 5
#define NS   10
#define H    10
#define PI2f 6.2831853071795864769f
// C = -0.5*(2pi)^2 * log2(e)  (fold exp->exp2)
#define CEXP (-28.47813296f)
#define ZITTER 1e-4f

// ---------------- device scratch ----------------
__device__ float2 g_tab[NB * NCH * NMIX * ND];   // (cos,sin)(2pi*mu_m*x_j)
__device__ float2 g_tabY[NB * NCH * NMIX * ND];  // y-premultiplied
__device__ float  g_xr[NB * NCH * ND];
#define NSEG 4
#define JSEG 192
__device__ float  g_fpart[NSEG][NB * ND * NCH * NMIX];
__device__ float  g_hpart[NB][6][30];            // k2a partial sums
__device__ float  g_w[NB * NCH * NMIX];

__device__ __forceinline__ float ex2f(float x) {
    float y;
    asm("ex2.approx.ftz.f32 %0, %1;" : "=f"(y) : "f"(x));
    return y;
}

// ============ Kernel 0: trig tables, parallel over (bc, m) ============
__global__ void k0_tables(const float* __restrict__ xc,
                          const float* __restrict__ yc,
                          const float* __restrict__ mu) {
    int bc = blockIdx.x;
    int m  = blockIdx.y;
    int b = bc / NCH, c = bc % NCH;
    int j = threadIdx.x;
    float x = xc[(b * ND + j) * NCH + c];
    float y = yc[(b * ND + j) * NCH + c];
    if (m == 0) g_xr[bc * ND + j] = x;
    float s, co;
    sincosf(PI2f * mu[m] * x, &s, &co);
    g_tab [(bc * NMIX + m) * ND + j] = make_float2(co, s);
    g_tabY[(bc * NMIX + m) * ND + j] = make_float2(co * y, s * y);
}

// ============ Kernel 1: feature partials (r4 proven) ============
// grid: x = 6 i-tiles * 4 j-segs, y = c, z = b; block = 128 (576 blocks)
__global__ void k1_feature(const float* __restrict__ inv_std) {
    __shared__ float  x_sh[JSEG];
    __shared__ float2 tabY[NMIX * JSEG];

    int seg  = blockIdx.x & 3;
    int tile = blockIdx.x >> 2;
    int c = blockIdx.y, b = blockIdx.z;
    int bc = b * NCH + c;
    int tid = threadIdx.x;
    int j0 = seg * JSEG;

    for (int t = tid; t < JSEG; t += 128)
        x_sh[t] = g_xr[bc * ND + j0 + t];
    for (int idx = tid; idx < NMIX * JSEG; idx += 128) {
        int m = idx / JSEG, jl = idx % JSEG;
        tabY[idx] = g_tabY[(bc * NMIX + m) * ND + j0 + jl];
    }
    __syncthreads();

    int i = tile * 128 + tid;
    float xi = g_xr[bc * ND + i];
    float ci[NMIX], si[NMIX], am[NMIX], acc[NMIX];
#pragma unroll
    for (int m = 0; m < NMIX; m++) {
        float2 cs = g_tab[(bc * NMIX + m) * ND + i];
        ci[m] = cs.x; si[m] = cs.y;
        float iv = __ldg(&inv_std[m]);
        am[m] = CEXP * iv * iv;
        acc[m] = 0.f;
    }

#pragma unroll 4
    for (int jl = 0; jl < JSEG; jl++) {
        float d = xi - x_sh[jl];
        float t = d * d;
#pragma unroll
        for (int m = 0; m < NMIX; m++) {
            float2 cy = tabY[m * JSEG + jl];
            float e = ex2f(am[m] * t);
            float p = fmaf(si[m], cy.y, ci[m] * cy.x);
            acc[m] = fmaf(e, p, acc[m]);
        }
    }

    int base = ((b * ND + i) * NCH + c) * NMIX;
#pragma unroll
    for (int m = 0; m < NMIX; m++)
        g_fpart[seg][base + m] = acc[m];
}

// ============ Kernel 2a: per-tile relu(W1*tif) partial sums ============
// grid (NB, 6), block 128. Each thread = one i row; sums 30 hidden units.
__global__ void k2a_partial(const float* __restrict__ yc,
                            const float* __restrict__ W1,
                            const float* __restrict__ b1) {
    __shared__ float s_part[128 * 30];
    __shared__ float s_r4[4 * 30];
    __shared__ float s_W1[60], s_b1[10];

    int b = blockIdx.x, tile = blockIdx.y;
    int tid = threadIdx.x;
    if (tid < 60) s_W1[tid] = W1[tid];
    if (tid < 10) s_b1[tid] = b1[tid];
    __syncthreads();

    int i = tile * 128 + tid;
    float acc30[30];
#pragma unroll
    for (int q = 0; q < 30; q++) acc30[q] = 0.f;

#pragma unroll
    for (int c = 0; c < NCH; c++) {
        int base = ((b * ND + i) * NCH + c) * NMIX;
        float y = yc[(b * ND + i) * NCH + c];
        float tif[6];
#pragma unroll
        for (int m = 0; m < NMIX; m++) {
            float f = ZITTER * y;
#pragma unroll
            for (int s = 0; s < NSEG; s++) f += g_fpart[s][base + m];
            tif[m] = f;
        }
        tif[5] = y;
#pragma unroll
        for (int k = 0; k < H; k++) {
            float h = s_b1[k];
#pragma unroll
            for (int q = 0; q < 6; q++) h = fmaf(tif[q], s_W1[k * 6 + q], h);
            acc30[c * H + k] += fmaxf(h, 0.f);
        }
    }
#pragma unroll
    for (int q = 0; q < 30; q++) s_part[tid * 30 + q] = acc30[q];
    __syncthreads();

    // 120 threads: q = tid%30, p = tid/30 (4 groups of 32 rows)
    if (tid < 120) {
        int q = tid % 30, p = tid / 30;
        float s = 0.f;
        int t0 = p * 32;
#pragma unroll 4
        for (int t = t0; t < t0 + 32; t++) s += s_part[t * 30 + q];
        s_r4[p * 30 + q] = s;
    }
    __syncthreads();
    if (tid < 30) {
        float s = s_r4[tid] + s_r4[30 + tid] + s_r4[60 + tid] + s_r4[90 + tid];
        g_hpart[b][tile][tid] = s;
    }
}

// ============ Kernel 2b: combine + MLP + Gumbel ============
// grid NB, block 32
__global__ void k2b_mlp(const float* __restrict__ unif,
                        const float* __restrict__ W2, const float* __restrict__ b2,
                        const float* __restrict__ W3, const float* __restrict__ b3,
                        const float* __restrict__ W4, const float* __restrict__ b4,
                        const float* __restrict__ W5, const float* __restrict__ b5) {
    __shared__ float s_hm[30];
    __shared__ float s_ha[10], s_hb[10];
    __shared__ float s_ll[15];

    int b = blockIdx.x;
    int tid = threadIdx.x;

    if (tid < 30) {
        float s = 0.f;
#pragma unroll
        for (int t = 0; t < 6; t++) s += g_hpart[b][t][tid];
        s_hm[tid] = s / (float)ND;
    }
    __syncthreads();
    if (tid < 10) {
        float v = b2[tid];
        for (int q = 0; q < 30; q++) v = fmaf(s_hm[q], W2[tid * 30 + q], v);
        s_ha[tid] = fmaxf(v, 0.f);
    }
    __syncthreads();
    if (tid < 10) {
        float v = b3[tid];
        for (int q = 0; q < 10; q++) v = fmaf(s_ha[q], W3[tid * 10 + q], v);
        s_hb[tid] = fmaxf(v, 0.f);
    }
    __syncthreads();
    if (tid < 10) {
        float v = b4[tid];
        for (int q = 0; q < 10; q++) v = fmaf(s_hb[q], W4[tid * 10 + q], v);
        s_ha[tid] = fmaxf(v, 0.f);
    }
    __syncthreads();
    if (tid < 15) {
        float v = b5[tid];
        for (int q = 0; q < 10; q++) v = fmaf(s_ha[q], W5[tid * 10 + q], v);
        s_ll[tid] = v;
    }
    __syncthreads();

    if (tid < 15) {
        int c = tid / NMIX, m = tid % NMIX;
        float wacc = 0.f;
        for (int s = 0; s < NS; s++) {
            float z[NMIX], zmax = -1e30f;
#pragma unroll
            for (int mp = 0; mp < NMIX; mp++) {
                float u = unif[((b * NS + s) * NCH + c) * NMIX + mp];
                float g = -logf(-logf(u + 1e-20f));
                z[mp] = (g + s_ll[c * NMIX + mp]) * 10.0f;
                zmax = fmaxf(zmax, z[mp]);
            }
            float denom = 0.f, em = 0.f;
#pragma unroll
            for (int mp = 0; mp < NMIX; mp++) {
                float e = __expf(z[mp] - zmax);
                denom += e;
                if (mp == m) em = e;
            }
            wacc += em / denom;
        }
        g_w[(b * NCH + c) * NMIX + m] = wacc / (float)NS;
    }
}

// ============ Kernel 3: weighted output (r4 proven, j-in-regs, i-tiled) ======
// grid = (3 j-segs, 24 i-tiles, 8 b), block = 256. One wave (576 blocks, 4/SM).
#define ITILE 32
__global__ void __launch_bounds__(256, 4) k3_weighted(
        const float* __restrict__ likerr,
        const float* __restrict__ inv_std,
        float* __restrict__ out) {
    __shared__ float  s_xi[ITILE * NCH];          // [ii][c]
    __shared__ float2 s_w2[ITILE * NCH * NMIX];   // [ii][c][m] = (w*cos_i, w*sin_i)

    int seg = blockIdx.x;
    int it  = blockIdx.y;
    int b   = blockIdx.z;
    int tid = threadIdx.x;
    int j   = seg * 256 + tid;
    int i0  = it * ITILE;

    // ---- j-side into registers ----
    float xj[NCH], cj[NCH][NMIX], sj[NCH][NMIX];
#pragma unroll
    for (int c = 0; c < NCH; c++) {
        int bc = b * NCH + c;
        xj[c] = g_xr[bc * ND + j];
#pragma unroll
        for (int m = 0; m < NMIX; m++) {
            float2 cs = g_tab[(bc * NMIX + m) * ND + j];
            cj[c][m] = cs.x; sj[c][m] = cs.y;
        }
    }
    float am[NMIX];
#pragma unroll
    for (int m = 0; m < NMIX; m++) {
        float iv = __ldg(&inv_std[m]);
        am[m] = CEXP * iv * iv;
    }
    float dg[NCH];
#pragma unroll
    for (int c = 0; c < NCH; c++) {
        float lv = fminf(fmaxf(__ldg(&likerr[c]), 0.1f), 1.0f);
        dg[c] = ZITTER + lv * lv;
    }

    // ---- stage i-side tile ----
    for (int t = tid; t < ITILE * NCH * NMIX; t += 256) {
        int ii = t / (NCH * NMIX);
        int cm = t % (NCH * NMIX);
        int c = cm / NMIX, m = cm % NMIX;
        int bc = b * NCH + c;
        float2 cs = g_tab[(bc * NMIX + m) * ND + (i0 + ii)];
        float ww = g_w[bc * NMIX + m];
        s_w2[t] = make_float2(ww * cs.x, ww * cs.y);
    }
    for (int t = tid; t < ITILE * NCH; t += 256) {
        int ii = t / NCH, c = t % NCH;
        s_xi[t] = g_xr[(b * NCH + c) * ND + (i0 + ii)];
    }
    __syncthreads();

    // ---- main loop over i tile ----
#pragma unroll 2
    for (int ii = 0; ii < ITILE; ii++) {
        int i = i0 + ii;
        float res[NCH];
#pragma unroll
        for (int c = 0; c < NCH; c++) {
            float d = s_xi[ii * NCH + c] - xj[c];
            float t2 = d * d;
            float acc = 0.f;
            int base = (ii * NCH + c) * NMIX;
#pragma unroll
            for (int m = 0; m < NMIX; m++) {
                float2 w2 = s_w2[base + m];
                float e = ex2f(am[m] * t2);
                float p = fmaf(w2.y, sj[c][m], w2.x * cj[c][m]);
                acc = fmaf(e, p, acc);
            }
            if (j == i) acc += dg[c];
            res[c] = acc;
        }
        long long obase = (((long long)(b * ND + i)) * ND + j) * NCH;
        out[obase + 0] = res[0];
        out[obase + 1] = res[1];
        out[obase + 2] = res[2];
    }
}

// ---------------- launch ----------------
extern "C" void kernel_launch(void* const* d_in, const int* in_sizes, int n_in,
                              void* d_out, int out_size) {
    const float* xc      = (const float*)d_in[0];
    const float* yc      = (const float*)d_in[1];
    const float* mu      = (const float*)d_in[2];
    const float* inv_std = (const float*)d_in[3];
    const float* likerr  = (const float*)d_in[4];
    const float* unif    = (const float*)d_in[5];
    const float* W1 = (const float*)d_in[6];
    const float* b1 = (const float*)d_in[7];
    const float* W2 = (const float*)d_in[8];
    const float* b2 = (const float*)d_in[9];
    const float* W3 = (const float*)d_in[10];
    const float* b3 = (const float*)d_in[11];
    const float* W4 = (const float*)d_in[12];
    const float* b4 = (const float*)d_in[13];
    const float* W5 = (const float*)d_in[14];
    const float* b5 = (const float*)d_in[15];
    float* out = (float*)d_out;

    k0_tables<<<dim3(NB * NCH, NMIX), ND>>>(xc, yc, mu);
    k1_feature<<<dim3(6 * NSEG, NCH, NB), 128>>>(inv_std);
    k2a_partial<<<dim3(NB, 6), 128>>>(yc, W1, b1);
    k2b_mlp<<<NB, 32>>>(unif, W2, b2, W3, b3, W4, b4, W5, b5);
    k3_weighted<<<dim3(3, ND / ITILE, NB), 256>>>(likerr, inv_std, out);
}

// round 11
// speedup vs baseline: 1.8283x; 1.0524x over previous
#include <cuda_runtime.h>
#include <math.h>

// ---------------- problem constants ----------------
#define NB   8
#define ND   768
#define NCH  3
#define NMIX 5
#define NS   10
#define H    10
#define PI2f 6.2831853071795864769f
// C = -0.5*(2pi)^2 * log2(e)  (fold exp->exp2)
#define CEXP (-28.47813296f)
#define ZITTER 1e-4f

// ---------------- device scratch ----------------
__device__ float2 g_tab[NB * NCH * NMIX * ND];   // (cos,sin)(2pi*mu_m*x_j)
__device__ float2 g_tabY[NB * NCH * NMIX * ND];  // y-premultiplied
__device__ float  g_xr[NB * NCH * ND];
#define NSEG 4
#define JSEG 192
__device__ float  g_fpart[NSEG][NB * ND * NCH * NMIX];
__device__ float  g_w[NB * NCH * NMIX];

__device__ __forceinline__ float ex2f(float x) {
    float y;
    asm("ex2.approx.ftz.f32 %0, %1;" : "=f"(y) : "f"(x));
    return y;
}

// ============ Kernel 0: trig tables, parallel over (bc, m) ============
__global__ void k0_tables(const float* __restrict__ xc,
                          const float* __restrict__ yc,
                          const float* __restrict__ mu) {
    int bc = blockIdx.x;
    int m  = blockIdx.y;
    int b = bc / NCH, c = bc % NCH;
    int j = threadIdx.x;
    float x = xc[(b * ND + j) * NCH + c];
    float y = yc[(b * ND + j) * NCH + c];
    if (m == 0) g_xr[bc * ND + j] = x;
    float s, co;
    sincosf(PI2f * mu[m] * x, &s, &co);
    g_tab [(bc * NMIX + m) * ND + j] = make_float2(co, s);
    g_tabY[(bc * NMIX + m) * ND + j] = make_float2(co * y, s * y);
}

// ============ Kernel 1: feature partials (r4 proven) ============
// grid: x = 6 i-tiles * 4 j-segs, y = c, z = b; block = 128 (576 blocks)
__global__ void k1_feature(const float* __restrict__ inv_std) {
    __shared__ float  x_sh[JSEG];
    __shared__ float2 tabY[NMIX * JSEG];

    int seg  = blockIdx.x & 3;
    int tile = blockIdx.x >> 2;
    int c = blockIdx.y, b = blockIdx.z;
    int bc = b * NCH + c;
    int tid = threadIdx.x;
    int j0 = seg * JSEG;

    for (int t = tid; t < JSEG; t += 128)
        x_sh[t] = g_xr[bc * ND + j0 + t];
    for (int idx = tid; idx < NMIX * JSEG; idx += 128) {
        int m = idx / JSEG, jl = idx % JSEG;
        tabY[idx] = g_tabY[(bc * NMIX + m) * ND + j0 + jl];
    }
    __syncthreads();

    int i = tile * 128 + tid;
    float xi = g_xr[bc * ND + i];
    float ci[NMIX], si[NMIX], am[NMIX], acc[NMIX];
#pragma unroll
    for (int m = 0; m < NMIX; m++) {
        float2 cs = g_tab[(bc * NMIX + m) * ND + i];
        ci[m] = cs.x; si[m] = cs.y;
        float iv = __ldg(&inv_std[m]);
        am[m] = CEXP * iv * iv;
        acc[m] = 0.f;
    }

#pragma unroll 4
    for (int jl = 0; jl < JSEG; jl++) {
        float d = xi - x_sh[jl];
        float t = d * d;
#pragma unroll
        for (int m = 0; m < NMIX; m++) {
            float2 cy = tabY[m * JSEG + jl];
            float e = ex2f(am[m] * t);
            float p = fmaf(si[m], cy.y, ci[m] * cy.x);
            acc[m] = fmaf(e, p, acc[m]);
        }
    }

    int base = ((b * ND + i) * NCH + c) * NMIX;
#pragma unroll
    for (int m = 0; m < NMIX; m++)
        g_fpart[seg][base + m] = acc[m];
}

// ============ Kernel 2: fused feature-MLP + Gumbel (grid NB, block 768) ======
__global__ void __launch_bounds__(768) k2_mlp(
        const float* __restrict__ yc,
        const float* __restrict__ unif,
        const float* __restrict__ W1, const float* __restrict__ b1,
        const float* __restrict__ W2, const float* __restrict__ b2,
        const float* __restrict__ W3, const float* __restrict__ b3,
        const float* __restrict__ W4, const float* __restrict__ b4,
        const float* __restrict__ W5, const float* __restrict__ b5) {
    __shared__ float s_wr[24 * 30];    // per-warp partial sums
    __shared__ float s_hm[30];
    __shared__ float s_ha[10], s_hb[10];
    __shared__ float s_ll[15];
    __shared__ float s_g[150];         // per-(sample, c*m) softmax values

    int b = blockIdx.x;
    int tid = threadIdx.x;
    int lane = tid & 31, w = tid >> 5;

    // ---- per-row W1 layer + relu, accumulate 30 hidden sums ----
    float acc30[30];
#pragma unroll
    for (int q = 0; q < 30; q++) acc30[q] = 0.f;
    {
        int i = tid;   // one row per thread
#pragma unroll
        for (int c = 0; c < NCH; c++) {
            int base = ((b * ND + i) * NCH + c) * NMIX;
            float y = yc[(b * ND + i) * NCH + c];
            float tif[6];
#pragma unroll
            for (int m = 0; m < NMIX; m++) {
                float f = ZITTER * y;
#pragma unroll
                for (int s = 0; s < NSEG; s++) f += g_fpart[s][base + m];
                tif[m] = f;
            }
            tif[5] = y;
#pragma unroll
            for (int k = 0; k < H; k++) {
                float h = __ldg(&b1[k]);
#pragma unroll
                for (int q = 0; q < 6; q++) h = fmaf(tif[q], __ldg(&W1[k * 6 + q]), h);
                acc30[c * H + k] += fmaxf(h, 0.f);
            }
        }
    }
    // ---- warp shuffle reduction ----
#pragma unroll
    for (int off = 16; off >= 1; off >>= 1) {
#pragma unroll
        for (int q = 0; q < 30; q++)
            acc30[q] += __shfl_down_sync(0xffffffffu, acc30[q], off);
    }
    if (lane == 0) {
#pragma unroll
        for (int q = 0; q < 30; q++) s_wr[w * 30 + q] = acc30[q];
    }
    __syncthreads();

    if (tid < 30) {
        float s = 0.f;
#pragma unroll
        for (int t = 0; t < 24; t++) s += s_wr[t * 30 + tid];
        s_hm[tid] = s / (float)ND;
    }
    __syncthreads();
    if (tid < 10) {
        float v = __ldg(&b2[tid]);
#pragma unroll
        for (int q = 0; q < 30; q++) v = fmaf(s_hm[q], __ldg(&W2[tid * 30 + q]), v);
        s_ha[tid] = fmaxf(v, 0.f);
    }
    __syncthreads();
    if (tid < 10) {
        float v = __ldg(&b3[tid]);
#pragma unroll
        for (int q = 0; q < 10; q++) v = fmaf(s_ha[q], __ldg(&W3[tid * 10 + q]), v);
        s_hb[tid] = fmaxf(v, 0.f);
    }
    __syncthreads();
    if (tid < 10) {
        float v = __ldg(&b4[tid]);
#pragma unroll
        for (int q = 0; q < 10; q++) v = fmaf(s_hb[q], __ldg(&W4[tid * 10 + q]), v);
        s_ha[tid] = fmaxf(v, 0.f);
    }
    __syncthreads();
    if (tid < 15) {
        float v = __ldg(&b5[tid]);
#pragma unroll
        for (int q = 0; q < 10; q++) v = fmaf(s_ha[q], __ldg(&W5[tid * 10 + q]), v);
        s_ll[tid] = v;
    }
    __syncthreads();

    // ---- Gumbel softmax: one thread per (sample, c*m) ----
    if (tid < 150) {
        int s  = tid / 15;
        int cm = tid % 15;
        int c = cm / NMIX, m = cm % NMIX;
        float z[NMIX], zmax = -1e30f;
#pragma unroll
        for (int mp = 0; mp < NMIX; mp++) {
            float u = __ldg(&unif[((b * NS + s) * NCH + c) * NMIX + mp]);
            float g = -__logf(-__logf(u + 1e-20f));
            z[mp] = (g + s_ll[c * NMIX + mp]) * 10.0f;   // /TEMP
            zmax = fmaxf(zmax, z[mp]);
        }
        float denom = 0.f, em = 0.f;
#pragma unroll
        for (int mp = 0; mp < NMIX; mp++) {
            float e = __expf(z[mp] - zmax);
            denom += e;
            if (mp == m) em = e;
        }
        s_g[tid] = em / denom;
    }
    __syncthreads();
    if (tid < 15) {
        float wacc = 0.f;
#pragma unroll
        for (int s = 0; s < NS; s++) wacc += s_g[s * 15 + tid];
        int c = tid / NMIX, m = tid % NMIX;
        g_w[(b * NCH + c) * NMIX + m] = wacc / (float)NS;
    }
}

// ============ Kernel 3: weighted output (r4 proven, j-in-regs, i-tiled) ======
// grid = (3 j-segs, 24 i-tiles, 8 b), block = 256. One wave (576 blocks, 4/SM).
#define ITILE 32
__global__ void __launch_bounds__(256, 4) k3_weighted(
        const float* __restrict__ likerr,
        const float* __restrict__ inv_std,
        float* __restrict__ out) {
    __shared__ float  s_xi[ITILE * NCH];          // [ii][c]
    __shared__ float2 s_w2[ITILE * NCH * NMIX];   // [ii][c][m] = (w*cos_i, w*sin_i)

    int seg = blockIdx.x;
    int it  = blockIdx.y;
    int b   = blockIdx.z;
    int tid = threadIdx.x;
    int j   = seg * 256 + tid;
    int i0  = it * ITILE;

    // ---- j-side into registers ----
    float xj[NCH], cj[NCH][NMIX], sj[NCH][NMIX];
#pragma unroll
    for (int c = 0; c < NCH; c++) {
        int bc = b * NCH + c;
        xj[c] = g_xr[bc * ND + j];
#pragma unroll
        for (int m = 0; m < NMIX; m++) {
            float2 cs = g_tab[(bc * NMIX + m) * ND + j];
            cj[c][m] = cs.x; sj[c][m] = cs.y;
        }
    }
    float am[NMIX];
#pragma unroll
    for (int m = 0; m < NMIX; m++) {
        float iv = __ldg(&inv_std[m]);
        am[m] = CEXP * iv * iv;
    }
    float dg[NCH];
#pragma unroll
    for (int c = 0; c < NCH; c++) {
        float lv = fminf(fmaxf(__ldg(&likerr[c]), 0.1f), 1.0f);
        dg[c] = ZITTER + lv * lv;
    }

    // ---- stage i-side tile ----
    for (int t = tid; t < ITILE * NCH * NMIX; t += 256) {
        int ii = t / (NCH * NMIX);
        int cm = t % (NCH * NMIX);
        int c = cm / NMIX, m = cm % NMIX;
        int bc = b * NCH + c;
        float2 cs = g_tab[(bc * NMIX + m) * ND + (i0 + ii)];
        float ww = g_w[bc * NMIX + m];
        s_w2[t] = make_float2(ww * cs.x, ww * cs.y);
    }
    for (int t = tid; t < ITILE * NCH; t += 256) {
        int ii = t / NCH, c = t % NCH;
        s_xi[t] = g_xr[(b * NCH + c) * ND + (i0 + ii)];
    }
    __syncthreads();

    // ---- main loop over i tile ----
#pragma unroll 2
    for (int ii = 0; ii < ITILE; ii++) {
        int i = i0 + ii;
        float res[NCH];
#pragma unroll
        for (int c = 0; c < NCH; c++) {
            float d = s_xi[ii * NCH + c] - xj[c];
            float t2 = d * d;
            float acc = 0.f;
            int base = (ii * NCH + c) * NMIX;
#pragma unroll
            for (int m = 0; m < NMIX; m++) {
                float2 w2 = s_w2[base + m];
                float e = ex2f(am[m] * t2);
                float p = fmaf(w2.y, sj[c][m], w2.x * cj[c][m]);
                acc = fmaf(e, p, acc);
            }
            if (j == i) acc += dg[c];
            res[c] = acc;
        }
        long long obase = (((long long)(b * ND + i)) * ND + j) * NCH;
        out[obase + 0] = res[0];
        out[obase + 1] = res[1];
        out[obase + 2] = res[2];
    }
}

// ---------------- launch ----------------
extern "C" void kernel_launch(void* const* d_in, const int* in_sizes, int n_in,
                              void* d_out, int out_size) {
    const float* xc      = (const float*)d_in[0];
    const float* yc      = (const float*)d_in[1];
    const float* mu      = (const float*)d_in[2];
    const float* inv_std = (const float*)d_in[3];
    const float* likerr  = (const float*)d_in[4];
    const float* unif    = (const float*)d_in[5];
    const float* W1 = (const float*)d_in[6];
    const float* b1 = (const float*)d_in[7];
    const float* W2 = (const float*)d_in[8];
    const float* b2 = (const float*)d_in[9];
    const float* W3 = (const float*)d_in[10];
    const float* b3 = (const float*)d_in[11];
    const float* W4 = (const float*)d_in[12];
    const float* b4 = (const float*)d_in[13];
    const float* W5 = (const float*)d_in[14];
    const float* b5 = (const float*)d_in[15];
    float* out = (float*)d_out;

    k0_tables<<<dim3(NB * NCH, NMIX), ND>>>(xc, yc, mu);
    k1_feature<<<dim3(6 * NSEG, NCH, NB), 128>>>(inv_std);
    k2_mlp<<<NB, 768>>>(yc, unif, W1, b1, W2, b2, W3, b3, W4, b4, W5, b5);
    k3_weighted<<<dim3(3, ND / ITILE, NB), 256>>>(likerr, inv_std, out);
}

// round 16
// speedup vs baseline: 1.8427x; 1.0079x over previous
#include <cuda_runtime.h>
#include <math.h>

// ---------------- problem constants ----------------
#define NB   8
#define ND   768
#define NCH  3
#define NMIX 5
#define NS   10
#define H    10
#define PI2f 6.2831853071795864769f
// C = -0.5*(2pi)^2 * log2(e)  (fold exp->exp2)
#define CEXP (-28.47813296f)
#define ZITTER 1e-4f

// ---------------- device scratch ----------------
__device__ float2 g_tab[NB * NCH * NMIX * ND];   // (cos,sin)(2pi*mu_m*x_j)
__device__ float  g_xr[NB * NCH * ND];
#define NSEG 4
#define JSEG 192
__device__ float  g_fpart[NSEG][NB * ND * NCH * NMIX];
__device__ float  g_w[NB * NCH * NMIX];

__device__ __forceinline__ float ex2f(float x) {
    float y;
    asm("ex2.approx.ftz.f32 %0, %1;" : "=f"(y) : "f"(x));
    return y;
}

// ============ Kernel 1: fused trig + feature partials ============
// grid: x = 6 i-tiles * 4 j-segs, y = c, z = b; block = 128 (576 blocks)
// Each block computes its own trig (__sincosf). Owner blocks (seg==tile&3)
// publish g_tab/g_xr for k3.
__global__ void k1_feature(const float* __restrict__ xc,
                           const float* __restrict__ yc,
                           const float* __restrict__ mu,
                           const float* __restrict__ inv_std) {
    // [jl*6 + m] = (cos*y, sin*y) for m<5 ; slot 5 = (xj, 0).  48B row stride.
    __shared__ __align__(16) float2 tj[JSEG * 6];

    int seg  = blockIdx.x & 3;
    int tile = blockIdx.x >> 2;
    int c = blockIdx.y, b = blockIdx.z;
    int bc = b * NCH + c;
    int tid = threadIdx.x;
    int j0 = seg * JSEG;

    float mus[NMIX];
#pragma unroll
    for (int m = 0; m < NMIX; m++) mus[m] = __ldg(&mu[m]);

    // ---- stage j-side (trig * y) ----
    for (int t = tid; t < JSEG; t += 128) {
        int j = j0 + t;
        float x = __ldg(&xc[(b * ND + j) * NCH + c]);
        float y = __ldg(&yc[(b * ND + j) * NCH + c]);
        tj[t * 6 + 5] = make_float2(x, 0.f);
#pragma unroll
        for (int m = 0; m < NMIX; m++) {
            float s, co;
            __sincosf(PI2f * mus[m] * x, &s, &co);
            tj[t * 6 + m] = make_float2(co * y, s * y);
        }
    }

    // ---- i-side in registers ----
    int i = tile * 128 + tid;
    float xi = __ldg(&xc[(b * ND + i) * NCH + c]);
    float ci[NMIX], si[NMIX], am[NMIX], acc[NMIX];
#pragma unroll
    for (int m = 0; m < NMIX; m++) {
        __sincosf(PI2f * mus[m] * xi, &si[m], &ci[m]);
        float iv = __ldg(&inv_std[m]);
        am[m] = CEXP * iv * iv;
        acc[m] = 0.f;
    }
    // owner block publishes tables for k3
    if (seg == (tile & 3)) {
        g_xr[bc * ND + i] = xi;
#pragma unroll
        for (int m = 0; m < NMIX; m++)
            g_tab[(bc * NMIX + m) * ND + i] = make_float2(ci[m], si[m]);
    }
    __syncthreads();

    // ---- main loop: 3x LDS.128 per jl ----
#pragma unroll 4
    for (int jl = 0; jl < JSEG; jl++) {
        const float4* q = (const float4*)&tj[jl * 6];
        float4 v0 = q[0];           // (cY0,sY0, cY1,sY1)
        float4 v1 = q[1];           // (cY2,sY2, cY3,sY3)
        float4 v2 = q[2];           // (cY4,sY4, xj, 0)
        float d = xi - v2.z;
        float t2 = d * d;
        float e, pr;
        e = ex2f(am[0] * t2); pr = fmaf(si[0], v0.y, ci[0] * v0.x); acc[0] = fmaf(e, pr, acc[0]);
        e = ex2f(am[1] * t2); pr = fmaf(si[1], v0.w, ci[1] * v0.z); acc[1] = fmaf(e, pr, acc[1]);
        e = ex2f(am[2] * t2); pr = fmaf(si[2], v1.y, ci[2] * v1.x); acc[2] = fmaf(e, pr, acc[2]);
        e = ex2f(am[3] * t2); pr = fmaf(si[3], v1.w, ci[3] * v1.z); acc[3] = fmaf(e, pr, acc[3]);
        e = ex2f(am[4] * t2); pr = fmaf(si[4], v2.y, ci[4] * v2.x); acc[4] = fmaf(e, pr, acc[4]);
    }

    int base = ((b * ND + i) * NCH + c) * NMIX;
#pragma unroll
    for (int m = 0; m < NMIX; m++)
        g_fpart[seg][base + m] = acc[m];
}

// ============ Kernel 2: fused feature-MLP + Gumbel (grid NB, block 768) ======
__global__ void __launch_bounds__(768) k2_mlp(
        const float* __restrict__ yc,
        const float* __restrict__ unif,
        const float* __restrict__ W1, const float* __restrict__ b1,
        const float* __restrict__ W2, const float* __restrict__ b2,
        const float* __restrict__ W3, const float* __restrict__ b3,
        const float* __restrict__ W4, const float* __restrict__ b4,
        const float* __restrict__ W5, const float* __restrict__ b5) {
    __shared__ float s_wr[24 * 30];    // per-warp partial sums
    __shared__ float s_hm[30];
    __shared__ float s_ha[10], s_hb[10];
    __shared__ float s_ll[15];
    __shared__ float s_g[150];         // per-(sample, c*m) softmax values

    int b = blockIdx.x;
    int tid = threadIdx.x;
    int lane = tid & 31, w = tid >> 5;

    float acc30[30];
#pragma unroll
    for (int q = 0; q < 30; q++) acc30[q] = 0.f;
    {
        int i = tid;
#pragma unroll
        for (int c = 0; c < NCH; c++) {
            int base = ((b * ND + i) * NCH + c) * NMIX;
            float y = yc[(b * ND + i) * NCH + c];
            float tif[6];
#pragma unroll
            for (int m = 0; m < NMIX; m++) {
                float f = ZITTER * y;
#pragma unroll
                for (int s = 0; s < NSEG; s++) f += g_fpart[s][base + m];
                tif[m] = f;
            }
            tif[5] = y;
#pragma unroll
            for (int k = 0; k < H; k++) {
                float h = __ldg(&b1[k]);
#pragma unroll
                for (int q = 0; q < 6; q++) h = fmaf(tif[q], __ldg(&W1[k * 6 + q]), h);
                acc30[c * H + k] += fmaxf(h, 0.f);
            }
        }
    }
#pragma unroll
    for (int off = 16; off >= 1; off >>= 1) {
#pragma unroll
        for (int q = 0; q < 30; q++)
            acc30[q] += __shfl_down_sync(0xffffffffu, acc30[q], off);
    }
    if (lane == 0) {
#pragma unroll
        for (int q = 0; q < 30; q++) s_wr[w * 30 + q] = acc30[q];
    }
    __syncthreads();

    if (tid < 30) {
        float s = 0.f;
#pragma unroll
        for (int t = 0; t < 24; t++) s += s_wr[t * 30 + tid];
        s_hm[tid] = s / (float)ND;
    }
    __syncthreads();
    if (tid < 10) {
        float v = __ldg(&b2[tid]);
#pragma unroll
        for (int q = 0; q < 30; q++) v = fmaf(s_hm[q], __ldg(&W2[tid * 30 + q]), v);
        s_ha[tid] = fmaxf(v, 0.f);
    }
    __syncthreads();
    if (tid < 10) {
        float v = __ldg(&b3[tid]);
#pragma unroll
        for (int q = 0; q < 10; q++) v = fmaf(s_ha[q], __ldg(&W3[tid * 10 + q]), v);
        s_hb[tid] = fmaxf(v, 0.f);
    }
    __syncthreads();
    if (tid < 10) {
        float v = __ldg(&b4[tid]);
#pragma unroll
        for (int q = 0; q < 10; q++) v = fmaf(s_hb[q], __ldg(&W4[tid * 10 + q]), v);
        s_ha[tid] = fmaxf(v, 0.f);
    }
    __syncthreads();
    if (tid < 15) {
        float v = __ldg(&b5[tid]);
#pragma unroll
        for (int q = 0; q < 10; q++) v = fmaf(s_ha[q], __ldg(&W5[tid * 10 + q]), v);
        s_ll[tid] = v;
    }
    __syncthreads();

    if (tid < 150) {
        int s  = tid / 15;
        int cm = tid % 15;
        int c = cm / NMIX, m = cm % NMIX;
        float z[NMIX], zmax = -1e30f;
#pragma unroll
        for (int mp = 0; mp < NMIX; mp++) {
            float u = __ldg(&unif[((b * NS + s) * NCH + c) * NMIX + mp]);
            float g = -__logf(-__logf(u + 1e-20f));
            z[mp] = (g + s_ll[c * NMIX + mp]) * 10.0f;   // /TEMP
            zmax = fmaxf(zmax, z[mp]);
        }
        float denom = 0.f, em = 0.f;
#pragma unroll
        for (int mp = 0; mp < NMIX; mp++) {
            float e = __expf(z[mp] - zmax);
            denom += e;
            if (mp == m) em = e;
        }
        s_g[tid] = em / denom;
    }
    __syncthreads();
    if (tid < 15) {
        float wacc = 0.f;
#pragma unroll
        for (int s = 0; s < NS; s++) wacc += s_g[s * 15 + tid];
        int c = tid / NMIX, m = tid % NMIX;
        g_w[(b * NCH + c) * NMIX + m] = wacc / (float)NS;
    }
}

// ============ Kernel 3: weighted output (j-in-regs, i-tiled, LDS.128) ======
// grid = (3 j-segs, 24 i-tiles, 8 b), block = 256. One wave (576 blocks, 4/SM).
#define ITILE 32
__global__ void __launch_bounds__(256, 4) k3_weighted(
        const float* __restrict__ likerr,
        const float* __restrict__ inv_std,
        float* __restrict__ out) {
    // [(ii*3+c)*6 + m] = (w*cos_i, w*sin_i) for m<5 ; slot 5 = (xi, 0)
    __shared__ __align__(16) float2 s_w2[ITILE * NCH * 6];

    int seg = blockIdx.x;
    int it  = blockIdx.y;
    int b   = blockIdx.z;
    int tid = threadIdx.x;
    int j   = seg * 256 + tid;
    int i0  = it * ITILE;

    // ---- j-side into registers ----
    float xj[NCH], cj[NCH][NMIX], sj[NCH][NMIX];
#pragma unroll
    for (int c = 0; c < NCH; c++) {
        int bc = b * NCH + c;
        xj[c] = g_xr[bc * ND + j];
#pragma unroll
        for (int m = 0; m < NMIX; m++) {
            float2 cs = g_tab[(bc * NMIX + m) * ND + j];
            cj[c][m] = cs.x; sj[c][m] = cs.y;
        }
    }
    float am[NMIX];
#pragma unroll
    for (int m = 0; m < NMIX; m++) {
        float iv = __ldg(&inv_std[m]);
        am[m] = CEXP * iv * iv;
    }
    float dg[NCH];
#pragma unroll
    for (int c = 0; c < NCH; c++) {
        float lv = fminf(fmaxf(__ldg(&likerr[c]), 0.1f), 1.0f);
        dg[c] = ZITTER + lv * lv;
    }

    // ---- stage i-side tile ----
    for (int t = tid; t < ITILE * NCH * NMIX; t += 256) {
        int ii = t / (NCH * NMIX);
        int cm = t % (NCH * NMIX);
        int c = cm / NMIX, m = cm % NMIX;
        int bc = b * NCH + c;
        float2 cs = g_tab[(bc * NMIX + m) * ND + (i0 + ii)];
        float ww = g_w[bc * NMIX + m];
        s_w2[(ii * NCH + c) * 6 + m] = make_float2(ww * cs.x, ww * cs.y);
    }
    for (int t = tid; t < ITILE * NCH; t += 256) {
        int ii = t / NCH, c = t % NCH;
        s_w2[(ii * NCH + c) * 6 + 5] =
            make_float2(g_xr[(b * NCH + c) * ND + (i0 + ii)], 0.f);
    }
    __syncthreads();

    // ---- main loop over i tile: 3x LDS.128 per (ii,c) ----
#pragma unroll 2
    for (int ii = 0; ii < ITILE; ii++) {
        int i = i0 + ii;
        float res[NCH];
#pragma unroll
        for (int c = 0; c < NCH; c++) {
            const float4* q = (const float4*)&s_w2[(ii * NCH + c) * 6];
            float4 v0 = q[0];       // (wc0,ws0, wc1,ws1)
            float4 v1 = q[1];       // (wc2,ws2, wc3,ws3)
            float4 v2 = q[2];       // (wc4,ws4, xi, 0)
            float d = v2.z - xj[c];
            float t2 = d * d;
            float acc = 0.f, e, p;
            e = ex2f(am[0] * t2); p = fmaf(v0.y, sj[c][0], v0.x * cj[c][0]); acc = fmaf(e, p, acc);
            e = ex2f(am[1] * t2); p = fmaf(v0.w, sj[c][1], v0.z * cj[c][1]); acc = fmaf(e, p, acc);
            e = ex2f(am[2] * t2); p = fmaf(v1.y, sj[c][2], v1.x * cj[c][2]); acc = fmaf(e, p, acc);
            e = ex2f(am[3] * t2); p = fmaf(v1.w, sj[c][3], v1.z * cj[c][3]); acc = fmaf(e, p, acc);
            e = ex2f(am[4] * t2); p = fmaf(v2.y, sj[c][4], v2.x * cj[c][4]); acc = fmaf(e, p, acc);
            if (j == i) acc += dg[c];
            res[c] = acc;
        }
        long long obase = (((long long)(b * ND + i)) * ND + j) * NCH;
        out[obase + 0] = res[0];
        out[obase + 1] = res[1];
        out[obase + 2] = res[2];
    }
}

// ---------------- launch ----------------
extern "C" void kernel_launch(void* const* d_in, const int* in_sizes, int n_in,
                              void* d_out, int out_size) {
    const float* xc      = (const float*)d_in[0];
    const float* yc      = (const float*)d_in[1];
    const float* mu      = (const float*)d_in[2];
    const float* inv_std = (const float*)d_in[3];
    const float* likerr  = (const float*)d_in[4];
    const float* unif    = (const float*)d_in[5];
    const float* W1 = (const float*)d_in[6];
    const float* b1 = (const float*)d_in[7];
    const float* W2 = (const float*)d_in[8];
    const float* b2 = (const float*)d_in[9];
    const float* W3 = (const float*)d_in[10];
    const float* b3 = (const float*)d_in[11];
    const float* W4 = (const float*)d_in[12];
    const float* b4 = (const float*)d_in[13];
    const float* W5 = (const float*)d_in[14];
    const float* b5 = (const float*)d_in[15];
    float* out = (float*)d_out;

    k1_feature<<<dim3(6 * NSEG, NCH, NB), 128>>>(xc, yc, mu, inv_std);
    k2_mlp<<<NB, 768>>>(yc, unif, W1, b1, W2, b2, W3, b3, W4, b4, W5, b5);
    k3_weighted<<<dim3(3, ND / ITILE, NB), 256>>>(likerr, inv_std, out);
}